// round 2
// baseline (speedup 1.0000x reference)
#include <cuda_runtime.h>
#include <cuda_fp16.h>
#include <cstdint>

#define BB 64
#define TSTEPS 512
#define HH 512
#define NCTA 128

// ---------------- static device scratch (no allocations allowed) ----------------
__device__ __align__(16) __half g_xh[TSTEPS * BB * 256];        // x cast fp16, [T][B][256]
__device__ __align__(16) __half g_h0[(TSTEPS + 1) * BB * HH];   // layer0 h seq, slot0 = 0
__device__ __align__(16) __half g_h1[(TSTEPS + 1) * BB * HH];   // layer1 h seq, slot0 = 0
__device__ unsigned g_cnt = 0;
__device__ unsigned g_gen = 0;

// ---------------- PTX helpers ----------------
__device__ __forceinline__ void cp16(uint32_t dst, const void* src) {
    asm volatile("cp.async.cg.shared.global [%0], [%1], 16;\n" :: "r"(dst), "l"(src));
}
__device__ __forceinline__ void cp_commit() { asm volatile("cp.async.commit_group;\n"); }
template<int N> __device__ __forceinline__ void cp_wait() {
    asm volatile("cp.async.wait_group %0;\n" :: "n"(N));
}
__device__ __forceinline__ void ldsm4(uint32_t& r0, uint32_t& r1, uint32_t& r2, uint32_t& r3,
                                      uint32_t a) {
    asm volatile("ldmatrix.sync.aligned.m8n8.x4.shared.b16 {%0,%1,%2,%3}, [%4];\n"
                 : "=r"(r0), "=r"(r1), "=r"(r2), "=r"(r3) : "r"(a));
}
__device__ __forceinline__ void mma16816(float* c,
                                         uint32_t a0, uint32_t a1, uint32_t a2, uint32_t a3,
                                         uint32_t b0, uint32_t b1) {
    asm volatile("mma.sync.aligned.m16n8k16.row.col.f32.f16.f16.f32 "
                 "{%0,%1,%2,%3}, {%4,%5,%6,%7}, {%8,%9}, {%0,%1,%2,%3};\n"
                 : "+f"(c[0]), "+f"(c[1]), "+f"(c[2]), "+f"(c[3])
                 : "r"(a0), "r"(a1), "r"(a2), "r"(a3), "r"(b0), "r"(b1));
}

// ---------------- A-chunk staging: 64 rows x 128 halves, swizzled ----------------
__device__ __forceinline__ void stage_chunk(uint32_t abuf, const __half* g, int gstride) {
    int tid = threadIdx.x;
#pragma unroll
    for (int i = 0; i < 4; i++) {
        int idx = tid + i * 256;
        int r = idx >> 4;
        int kc = idx & 15;
        cp16(abuf + r * 256 + ((kc ^ (r & 7)) << 4), g + r * gstride + kc * 8);
    }
}

// ---------------- one GEMM accumulation phase: acc += A[64,K] @ Wslice(kb0..)^T ----------------
template<int KCHUNKS>
__device__ __forceinline__ void gemm_phase(float* acc, const __half* g, int gstride,
                                           uint32_t asmb, uint32_t wsmb, int wrowb, int kb0) {
    int tid  = threadIdx.x;
    int lane = tid & 31;
    int w    = tid >> 5;
    int m0 = (w & 3) * 16;
    int n0 = (w >> 2) * 8;
    int rA = m0 + (lane & 15);
    uint32_t abase = asmb + rA * 256;
    int asw = rA & 7;
    int akc = lane >> 4;
    int rB = n0 + (lane & 7);
    uint32_t bbase = wsmb + rB * wrowb;
    int bsw = rB & 7;
    int bm = lane >> 3;

    stage_chunk(asmb, g, gstride);
    cp_commit();
#pragma unroll
    for (int c = 0; c < KCHUNKS; c++) {
        if (c + 1 < KCHUNKS) {
            stage_chunk(asmb + ((c + 1) & 1) * 16384, g + (c + 1) * 128, gstride);
            cp_commit();
            cp_wait<1>();
        } else {
            cp_wait<0>();
        }
        __syncthreads();
        uint32_t ab = abase + (c & 1) * 16384;
        int kcc = (kb0 >> 3) + c * 16 + bm;
#pragma unroll
        for (int j = 0; j < 8; j += 2) {
            uint32_t b0, b1, b2, b3, a0, a1, a2, a3;
            ldsm4(b0, b1, b2, b3, bbase + (((kcc + 2 * j) ^ bsw) << 4));
            ldsm4(a0, a1, a2, a3, ab + (((2 * j + akc) ^ asw) << 4));
            mma16816(acc, a0, a1, a2, a3, b0, b1);
            ldsm4(a0, a1, a2, a3, ab + (((2 * j + 2 + akc) ^ asw) << 4));
            mma16816(acc, a0, a1, a2, a3, b2, b3);
        }
        __syncthreads();
    }
}

// ---------------- prep kernels ----------------
__global__ void prep_x_k(const float* __restrict__ x) {
    int i = blockIdx.x * 256 + threadIdx.x;   // one float2 each; B*T*F/2 = 4194304
    int f2 = i & 127;
    int t  = (i >> 7) & 511;
    int b  = i >> 16;
    float2 v = *(const float2*)(x + ((b * 512 + t) * 256 + f2 * 2));
    *((__half2*)(g_xh + (t * 64 + b) * 256 + f2 * 2)) = __floats2half2_rn(v.x, v.y);
}

__global__ void zero_k() {
    int i = blockIdx.x * 256 + threadIdx.x;   // 16384 threads -> B*H halves per buffer
    __half2 z = __floats2half2_rn(0.f, 0.f);
    ((__half2*)g_h0)[i] = z;
    ((__half2*)g_h1)[i] = z;
}

// ---------------- persistent recurrent layer kernel ----------------
template<int LAYER>
__global__ void __launch_bounds__(256, 1) lstm_k(
    const float* __restrict__ Wih, const float* __restrict__ Whh,
    const float* __restrict__ bih, const float* __restrict__ bhh,
    float* __restrict__ outp) {
    constexpr int KIN  = (LAYER == 0) ? 256 : 512;
    constexpr int KTOT = KIN + 512;
    constexpr int ROWB = KTOT * 2;                 // W smem row bytes
    constexpr int ASM_OFF = 16 * KTOT * 2;         // after W slice
    constexpr int GSM_OFF = ASM_OFF + 32768;       // after 2x16KB A buffers

    const __half* xin = (LAYER == 0) ? g_xh : (g_h0 + BB * HH);
    __half* hbuf      = (LAYER == 0) ? g_h0 : g_h1;

    extern __shared__ char dsm[];
    uint32_t smb  = (uint32_t)__cvta_generic_to_shared(dsm);
    uint32_t wsmb = smb;
    uint32_t asmb = smb + ASM_OFF;
    float* gsm = (float*)(dsm + GSM_OFF);          // [64][16] gate stash

    int tid = threadIdx.x;
    int bx  = blockIdx.x;

    // ---- load & convert this CTA's 16 W rows ([Wih | Whh] along k), swizzled fp16 ----
    for (int idx = tid; idx < 16 * KTOT / 4; idx += 256) {
        int n  = idx / (KTOT / 4);
        int kk = (idx % (KTOT / 4)) * 4;
        int gr = (n >> 2) * HH + bx * 4 + (n & 3);
        float4 v = (kk < KIN) ? *(const float4*)(Wih + gr * KIN + kk)
                              : *(const float4*)(Whh + gr * 512 + (kk - KIN));
        __half2 p0 = __floats2half2_rn(v.x, v.y);
        __half2 p1 = __floats2half2_rn(v.z, v.w);
        char* dst = dsm + n * ROWB + (((kk >> 3) ^ (n & 7)) << 4) + (kk & 7) * 2;
        *(__half2*)dst       = p0;
        *(__half2*)(dst + 4) = p1;
    }

    // ---- per-thread combined bias for this warp's two C columns ----
    int lane = tid & 31;
    int w    = tid >> 5;
    int m0 = (w & 3) * 16;
    int n0 = (w >> 2) * 8;
    int col0 = n0 + 2 * (lane & 3);
    int col1 = col0 + 1;
    float bias0 = bih[(col0 >> 2) * HH + bx * 4 + (col0 & 3)]
                + bhh[(col0 >> 2) * HH + bx * 4 + (col0 & 3)];
    float bias1 = bih[(col1 >> 2) * HH + bx * 4 + (col1 & 3)]
                + bhh[(col1 >> 2) * HH + bx * 4 + (col1 & 3)];
    __syncthreads();

    float cst = 0.f;                               // c-state for (b=tid>>2, u=tid&3)
    float acc[4] = {bias0, bias1, bias0, bias1};
    // prologue: x-contribution for step 1
    gemm_phase<KIN / 128>(acc, xin, KIN, asmb, wsmb, ROWB, 0);

    for (int t = 1; t <= TSTEPS; t++) {
        // h-contribution (critical path), K = 512
        gemm_phase<4>(acc, hbuf + (t - 1) * BB * HH, HH, asmb, wsmb, ROWB, KIN);

        // stash gates to smem
        int gid = lane >> 2, tig = lane & 3;
        float* s0 = gsm + (m0 + gid) * 16 + n0 + 2 * tig;
        s0[0] = acc[0]; s0[1] = acc[1];
        float* s1 = gsm + (m0 + 8 + gid) * 16 + n0 + 2 * tig;
        s1[0] = acc[2]; s1[1] = acc[3];
        __syncthreads();

        // pointwise LSTM cell: thread owns (b, u)
        int bb = tid >> 2, uu = tid & 3;
        float zi = gsm[bb * 16 + uu];
        float zf = gsm[bb * 16 + 4 + uu];
        float zg = gsm[bb * 16 + 8 + uu];
        float zo = gsm[bb * 16 + 12 + uu];
        float ival = 1.f / (1.f + __expf(-zi));
        float fval = 1.f / (1.f + __expf(-zf));
        float gval = tanhf(zg);
        float oval = 1.f / (1.f + __expf(-zo));
        cst = fval * cst + ival * gval;
        float hv = oval * tanhf(cst);
        hbuf[t * BB * HH + bb * HH + bx * 4 + uu] = __float2half(hv);
        if (LAYER == 1) outp[(bb * TSTEPS + (t - 1)) * HH + bx * 4 + uu] = hv;
        __syncthreads();

        if (t < TSTEPS) {
            // arrive at grid barrier, compute next step's x-contribution, then wait
            unsigned my = 0;
            if (tid == 0) {
                my = *(volatile unsigned*)&g_gen;
                __threadfence();
                if (atomicAdd(&g_cnt, 1u) == NCTA - 1) {
                    atomicExch(&g_cnt, 0u);
                    __threadfence();
                    *(volatile unsigned*)&g_gen = my + 1;
                }
            }
            acc[0] = bias0; acc[1] = bias1; acc[2] = bias0; acc[3] = bias1;
            gemm_phase<KIN / 128>(acc, xin + t * BB * KIN, KIN, asmb, wsmb, ROWB, 0);
            if (tid == 0) {
                while (*(volatile unsigned*)&g_gen == my) { }
                __threadfence();
            }
            __syncthreads();
        }
    }
}

// ---------------- host launcher ----------------
extern "C" void kernel_launch(void* const* d_in, const int* in_sizes, int n_in,
                              void* d_out, int out_size) {
    const float* x    = (const float*)d_in[0];
    const float* Wih0 = (const float*)d_in[1];
    const float* Whh0 = (const float*)d_in[2];
    const float* bih0 = (const float*)d_in[3];
    const float* bhh0 = (const float*)d_in[4];
    const float* Wih1 = (const float*)d_in[5];
    const float* Whh1 = (const float*)d_in[6];
    const float* bih1 = (const float*)d_in[7];
    const float* bhh1 = (const float*)d_in[8];
    float* out = (float*)d_out;

    cudaFuncSetAttribute(lstm_k<0>, cudaFuncAttributeMaxDynamicSharedMemorySize, 61440);
    cudaFuncSetAttribute(lstm_k<1>, cudaFuncAttributeMaxDynamicSharedMemorySize, 69632);

    prep_x_k<<<16384, 256>>>(x);
    zero_k<<<64, 256>>>();
    lstm_k<0><<<NCTA, 256, 61440>>>(Wih0, Whh0, bih0, bhh0, nullptr);
    lstm_k<1><<<NCTA, 256, 69632>>>(Wih1, Whh1, bih1, bhh1, out);
}